// round 7
// baseline (speedup 1.0000x reference)
#include <cuda_runtime.h>

#define FULL 0xffffffffu
#define NW 10

// layer-1 Rot matrices (per wire, 8 floats)
__device__ float  g_rot1[NW * 8];
// scratch: per BIT k (bit k <-> wire 9-k): M = U^H P U for layer-2 gate on that bit
__device__ float2 g_MZ[NW * 4];   // [k*4 + r*2 + c]
__device__ float2 g_MX[NW * 4];
// per-lane site-matrix table: Mtab[f][k][4] and feature weights
__device__ float2 g_Mtab[32][NW][4];
__device__ float  g_wt[32];

__global__ void prep_kernel(const float* __restrict__ params,
                            const float* __restrict__ head_w) {
    int k = threadIdx.x;
    if (k < NW) {
        // layer-1 Rot for wire k
        float phi = params[k * 3 + 0], th = params[k * 3 + 1], om = params[k * 3 + 2];
        float ct, st, cp, sp, cm, sm;
        sincosf(0.5f * th, &st, &ct);
        sincosf(0.5f * (phi + om), &sp, &cp);
        sincosf(0.5f * (phi - om), &sm, &cm);
        float* o = &g_rot1[k * 8];
        o[0] =  ct * cp;  o[1] = -ct * sp;
        o[2] = -st * cm;  o[3] = -st * sm;
        o[4] =  st * cm;  o[5] = -st * sm;
        o[6] =  ct * cp;  o[7] =  ct * sp;

        // layer-2 gate on bit k is the Rot of wire w = 9-k
        int w = 9 - k;
        float phi2 = params[(NW + w) * 3 + 0], th2 = params[(NW + w) * 3 + 1], om2 = params[(NW + w) * 3 + 2];
        sincosf(0.5f * th2, &st, &ct);
        sincosf(0.5f * (phi2 + om2), &sp, &cp);
        sincosf(0.5f * (phi2 - om2), &sm, &cm);
        float U[2][2][2];
        U[0][0][0] =  ct * cp;  U[0][0][1] = -ct * sp;
        U[0][1][0] = -st * cm;  U[0][1][1] = -st * sm;
        U[1][0][0] =  st * cm;  U[1][0][1] = -st * sm;
        U[1][1][0] =  ct * cp;  U[1][1][1] =  ct * sp;
        for (int r = 0; r < 2; ++r)
            for (int c = 0; c < 2; ++c) {
                float a0r = U[0][r][0], a0i = U[0][r][1];
                float a1r = U[1][r][0], a1i = U[1][r][1];
                float b0r = U[0][c][0], b0i = U[0][c][1];
                float b1r = U[1][c][0], b1i = U[1][c][1];
                float z0r = a0r * b0r + a0i * b0i, z0i = a0r * b0i - a0i * b0r;  // conj(a0)b0
                float z1r = a1r * b1r + a1i * b1i, z1i = a1r * b1i - a1i * b1r;  // conj(a1)b1
                g_MZ[k * 4 + r * 2 + c] = make_float2(z0r - z1r, z0i - z1i);
                float y0r = a0r * b1r + a0i * b1i, y0i = a0r * b1i - a0i * b1r;  // conj(a0)b1
                float y1r = a1r * b0r + a1i * b0i, y1i = a1r * b0i - a1i * b0r;  // conj(a1)b0
                g_MX[k * 4 + r * 2 + c] = make_float2(y0r + y1r, y0i + y1i);
            }
    }
    __syncthreads();

    // Phase 2: thread f builds its feature row
    int f = threadIdx.x;   // 0..31
    for (int kk = 0; kk < NW; ++kk) {
        float2 m0 = make_float2(1.f, 0.f), m1 = make_float2(0.f, 0.f);
        float2 m2 = make_float2(0.f, 0.f), m3 = make_float2(1.f, 0.f);
        bool useZ = false, useX = false;
        if (f < 10) {
            // Z feature for wire w=f: MZ on bits >= 9-w
            useZ = (kk >= 9 - f);
        } else if (f < 20) {
            int w = f - 10;
            if (w == 9) useX = (kk == 0);
            else        useX = (kk == 8 - w) || (kk == 9 - w);
        }
        if (useZ) {
            m0 = g_MZ[kk * 4 + 0]; m1 = g_MZ[kk * 4 + 1];
            m2 = g_MZ[kk * 4 + 2]; m3 = g_MZ[kk * 4 + 3];
        } else if (useX) {
            m0 = g_MX[kk * 4 + 0]; m1 = g_MX[kk * 4 + 1];
            m2 = g_MX[kk * 4 + 2]; m3 = g_MX[kk * 4 + 3];
        }
        g_Mtab[f][kk][0] = m0; g_Mtab[f][kk][1] = m1;
        g_Mtab[f][kk][2] = m2; g_Mtab[f][kk][3] = m3;
    }
    g_wt[f] = (f < 20) ? head_w[f] : 0.f;
}

// ---- packed f32x2 complex helpers ----
__device__ __forceinline__ unsigned long long f2u(float2 v) {
    unsigned long long r;
    asm("mov.b64 %0, {%1,%2};" : "=l"(r) : "f"(v.x), "f"(v.y));
    return r;
}
__device__ __forceinline__ float2 u2f(unsigned long long r) {
    float2 v;
    asm("mov.b64 {%0,%1}, %2;" : "=f"(v.x), "=f"(v.y) : "l"(r));
    return v;
}
__device__ __forceinline__ float2 fma2(float2 a, float2 b, float2 c) {
    unsigned long long r, ua = f2u(a), ub = f2u(b), uc = f2u(c);
    asm("fma.rn.f32x2 %0, %1, %2, %3;" : "=l"(r) : "l"(ua), "l"(ub), "l"(uc));
    return u2f(r);
}
__device__ __forceinline__ float2 mul2(float2 a, float2 b) {
    unsigned long long r, ua = f2u(a), ub = f2u(b);
    asm("mul.rn.f32x2 %0, %1, %2;" : "=l"(r) : "l"(ua), "l"(ub));
    return u2f(r);
}
__device__ __forceinline__ float2 sw2(float2 a) { return make_float2(a.y, a.x); }
// a*b
__device__ __forceinline__ float2 cmul(float2 a, float2 b) {
    return fma2(make_float2(-a.y, a.y), sw2(b), mul2(make_float2(a.x, a.x), b));
}
// a*b + c
__device__ __forceinline__ float2 cmula(float2 a, float2 b, float2 c) {
    return fma2(make_float2(-a.y, a.y), sw2(b), fma2(make_float2(a.x, a.x), b, c));
}
// conj(a)*b
__device__ __forceinline__ float2 cjmul(float2 a, float2 b) {
    return fma2(make_float2(a.y, -a.y), sw2(b), mul2(make_float2(a.x, a.x), b));
}
// conj(a)*b + c
__device__ __forceinline__ float2 cjmula(float2 a, float2 b, float2 c) {
    return fma2(make_float2(a.y, -a.y), sw2(b), fma2(make_float2(a.x, a.x), b, c));
}

__global__ __launch_bounds__(256) void qreg_kernel(
    const float* __restrict__ x,        // (B, 10)
    const float* __restrict__ head_b,   // (1,)
    float* __restrict__ out,            // (B,)
    int B)
{
    const int gwarp = (blockIdx.x * 256 + threadIdx.x) >> 5;  // sample index
    const int lane  = threadIdx.x & 31;                       // feature index
    if (gwarp >= B) return;
    const float* xb = x + gwarp * NW;

    // ---- per-bit 1-qubit factors g_k(0), g_k(1): bit k <-> wire 9-k ----
    float2 g0[NW], g1[NW];
    #pragma unroll
    for (int w = 0; w < NW; ++w) {
        float cx, sx;
        __sincosf(0.5f * __ldg(&xb[w]), &sx, &cx);
        const float* gp = &g_rot1[w * 8];
        g0[9 - w] = make_float2(__ldg(gp + 0) * cx + __ldg(gp + 2) * sx,
                                __ldg(gp + 1) * cx + __ldg(gp + 3) * sx);
        g1[9 - w] = make_float2(__ldg(gp + 4) * cx + __ldg(gp + 6) * sx,
                                __ldg(gp + 5) * cx + __ldg(gp + 7) * sx);
    }

    // ---- uniform transfer-matrix contraction, right-to-left ----
    // r[(i_k, j_k)] ; boundary (i_10, j_10) = (0,0)
    float2 r0 = make_float2(1.f, 0.f), r1 = make_float2(0.f, 0.f);
    float2 r2 = make_float2(0.f, 0.f), r3 = make_float2(0.f, 0.f);
    const float2* Mrow = &g_Mtab[lane][0][0];
    #pragma unroll
    for (int k = 9; k >= 0; --k) {
        const float2 ga = g0[k], gb = g1[k];
        // h[i_k][j_{k+1}] = sum_{i_{k+1}} conj(g(i_k ^ i_{k+1})) r[(i_{k+1}, j_{k+1})]
        const float2 h00 = cjmula(ga, r0, cjmul(gb, r2));
        const float2 h01 = cjmula(ga, r1, cjmul(gb, r3));
        const float2 h10 = cjmula(gb, r0, cjmul(ga, r2));
        const float2 h11 = cjmula(gb, r1, cjmul(ga, r3));
        // t[(i_k, j_k)] = sum_{j_{k+1}} g(j_k ^ j_{k+1}) h[i_k][j_{k+1}]
        const float2 t00 = cmula(ga, h00, cmul(gb, h01));
        const float2 t01 = cmula(gb, h00, cmul(ga, h01));
        const float2 t10 = cmula(ga, h10, cmul(gb, h11));
        const float2 t11 = cmula(gb, h10, cmul(ga, h11));
        // elementwise site operator M[i_k][j_k]
        r0 = cmul(__ldg(&Mrow[k * 4 + 0]), t00);
        r1 = cmul(__ldg(&Mrow[k * 4 + 1]), t01);
        r2 = cmul(__ldg(&Mrow[k * 4 + 2]), t10);
        r3 = cmul(__ldg(&Mrow[k * 4 + 3]), t11);
    }

    // feature value = Re( sum over (i_0, j_0) )
    const float F = r0.x + r1.x + r2.x + r3.x;
    float partial = __ldg(&g_wt[lane]) * F;

    // warp reduction over 20 active features (lanes 20..31 contribute 0)
    #pragma unroll
    for (int o = 16; o > 0; o >>= 1)
        partial += __shfl_xor_sync(FULL, partial, o);
    if (lane == 0) out[gwarp] = partial + __ldg(head_b);
}

extern "C" void kernel_launch(void* const* d_in, const int* in_sizes, int n_in,
                              void* d_out, int out_size) {
    const float* x      = (const float*)d_in[0];  // (B,10)
    const float* params = (const float*)d_in[1];  // (60,)
    const float* hw     = (const float*)d_in[2];  // (20,)
    const float* hb     = (const float*)d_in[3];  // (1,)
    float* out = (float*)d_out;
    const int B = in_sizes[0] / NW;               // 4096

    prep_kernel<<<1, 32>>>(params, hw);
    const int warps_per_blk = 8;                  // 256 threads
    const int blocks = (B + warps_per_blk - 1) / warps_per_blk;
    qreg_kernel<<<blocks, warps_per_blk * 32>>>(x, hb, out, B);
}

// round 8
// speedup vs baseline: 2.9462x; 2.9462x over previous
#include <cuda_runtime.h>

#define NW 10

// layer-1 Rot matrices (per wire, 8 floats {u00r,u00i,u01r,u01i,u10r,u10i,u11r,u11i})
__device__ float  g_rot1[NW * 8];
// Hermitian-compressed layer-2 conjugated Paulis, per BIT k (bit k <-> wire 9-k):
//   (m00, m01r, m01i, m11)  with m10 = conj(m01), m00/m11 real
__device__ float4 g_MZh[NW];
__device__ float4 g_MXh[NW];

__global__ void prep_kernel(const float* __restrict__ params) {
    int k = threadIdx.x;
    if (k >= NW) return;

    // layer-1 Rot for wire k
    {
        float phi = params[k * 3 + 0], th = params[k * 3 + 1], om = params[k * 3 + 2];
        float ct, st, cp, sp, cm, sm;
        sincosf(0.5f * th, &st, &ct);
        sincosf(0.5f * (phi + om), &sp, &cp);
        sincosf(0.5f * (phi - om), &sm, &cm);
        float* o = &g_rot1[k * 8];
        o[0] =  ct * cp;  o[1] = -ct * sp;
        o[2] = -st * cm;  o[3] = -st * sm;
        o[4] =  st * cm;  o[5] = -st * sm;
        o[6] =  ct * cp;  o[7] =  ct * sp;
    }

    // layer-2 gate on bit k is the Rot of wire w = 9-k
    {
        int w = 9 - k;
        float phi = params[(NW + w) * 3 + 0], th = params[(NW + w) * 3 + 1], om = params[(NW + w) * 3 + 2];
        float ct, st, cp, sp, cm, sm;
        sincosf(0.5f * th, &st, &ct);
        sincosf(0.5f * (phi + om), &sp, &cp);
        sincosf(0.5f * (phi - om), &sm, &cm);
        // U[row][col] complex
        float U00r =  ct * cp, U00i = -ct * sp;
        float U01r = -st * cm, U01i = -st * sm;
        float U10r =  st * cm, U10i = -st * sm;
        float U11r =  ct * cp, U11i =  ct * sp;

        // MZ = U^H Z U :  MZ00 = |U00|^2 - |U10|^2 ; MZ11 = |U01|^2 - |U11|^2
        //                 MZ01 = conj(U00)U01 - conj(U10)U11
        float mz00 = (U00r * U00r + U00i * U00i) - (U10r * U10r + U10i * U10i);
        float mz11 = (U01r * U01r + U01i * U01i) - (U11r * U11r + U11i * U11i);
        float mz01r = (U00r * U01r + U00i * U01i) - (U10r * U11r + U10i * U11i);
        float mz01i = (U00r * U01i - U00i * U01r) - (U10r * U11i - U10i * U11r);
        g_MZh[k] = make_float4(mz00, mz01r, mz01i, mz11);

        // MX = U^H X U :  MX00 = 2 Re(conj(U00)U10) ; MX11 = 2 Re(conj(U01)U11)
        //                 MX01 = conj(U00)U11 + conj(U10)U01
        float mx00 = 2.f * (U00r * U10r + U00i * U10i);
        float mx11 = 2.f * (U01r * U11r + U01i * U11i);
        float mx01r = (U00r * U11r + U00i * U11i) + (U10r * U01r + U10i * U01i);
        float mx01i = (U00r * U11i - U00i * U11r) + (U10r * U01i - U10i * U01r);
        g_MXh[k] = make_float4(mx00, mx01r, mx01i, mx11);
    }
}

// Hermitian 2x2: (a, br, bi, c) with [ [a, b], [conj(b), c] ], a/c real.
struct H { float a, br, bi, c; };

// Full sandwich step: t = A^H r A using per-site constants, then elementwise M.
__device__ __forceinline__ H sandwich_m(const H r, float n0, float n1,
                                        float er, float ei, float4 M) {
    const float cross_m = er * r.br - ei * r.bi;   // Re(e * b)
    const float cross_p = er * r.br + ei * r.bi;   // Re(e * conj(b))
    const float t00 = n0 * r.a + n1 * r.c + 2.f * cross_m;
    const float t11 = n1 * r.a + n0 * r.c + 2.f * cross_p;
    const float t01r = (r.a + r.c) * er + (n0 + n1) * r.br;
    const float t01i = (r.a - r.c) * ei + (n0 - n1) * r.bi;
    H o;
    o.a  = M.x * t00;
    o.c  = M.w * t11;
    o.br = M.y * t01r - M.z * t01i;
    o.bi = M.y * t01i + M.z * t01r;
    return o;
}

// Sandwich step from a DIAGONAL input (sA, sB), then elementwise M.
__device__ __forceinline__ H diagstep_m(float sA, float sB, float n0, float n1,
                                        float er, float ei, float4 M) {
    const float t00 = n0 * sA + n1 * sB;
    const float t11 = n1 * sA + n0 * sB;
    const float t01r = (sA + sB) * er;
    const float t01i = (sA - sB) * ei;
    H o;
    o.a  = M.x * t00;
    o.c  = M.w * t11;
    o.br = M.y * t01r - M.z * t01i;
    o.bi = M.y * t01i + M.z * t01r;
    return o;
}

// dot of two Hermitian objects: Re( sum_{ij} L[ij] R[ij] )
__device__ __forceinline__ float hdot(float la, float lbr, float lbi, float lc, const H r) {
    return la * r.a + lc * r.c + 2.f * (lbr * r.br - lbi * r.bi);
}

__global__ __launch_bounds__(32) void qreg_kernel(
    const float* __restrict__ x,        // (B, 10)
    const float* __restrict__ head_w,   // (20,)
    const float* __restrict__ head_b,   // (1,)
    float* __restrict__ out,            // (B,)
    int B)
{
    const int b = blockIdx.x * 32 + threadIdx.x;
    if (b >= B) return;

    // ---- per-bit 1-qubit factors g0,g1 (bit k <-> wire 9-k) ----
    float g0r[NW], g0i[NW], g1r[NW], g1i[NW];
    #pragma unroll
    for (int w = 0; w < NW; ++w) {
        float cx, sx;
        __sincosf(0.5f * __ldg(&x[b * NW + w]), &sx, &cx);
        const float* gp = &g_rot1[w * 8];
        const int k = 9 - w;
        g0r[k] = __ldg(gp + 0) * cx + __ldg(gp + 2) * sx;
        g0i[k] = __ldg(gp + 1) * cx + __ldg(gp + 3) * sx;
        g1r[k] = __ldg(gp + 4) * cx + __ldg(gp + 6) * sx;
        g1i[k] = __ldg(gp + 5) * cx + __ldg(gp + 7) * sx;
    }

    // ---- suffix sweep (k = 9 .. 0) ----
    // Z object (all-MZ suffix), identity diag (sA, sB), X-pair objects XX_k,
    // and single-site X objects XA_k (XA_0 = lone-X feature object).
    H Zs[NW];       // Z suffix after including site k
    H XX[NW - 1];   // X-pair object for pair (k, k+1), k = 0..8
    H z;  z.a = 1.f; z.br = 0.f; z.bi = 0.f; z.c = 0.f;   // boundary diag(1,0)
    float sA = 1.f, sB = 0.f;
    H xa_prev;      // XA_{k+1} from previous iteration

    #pragma unroll
    for (int k = 9; k >= 0; --k) {
        const float n0 = g0r[k] * g0r[k] + g0i[k] * g0i[k];
        const float n1 = g1r[k] * g1r[k] + g1i[k] * g1i[k];
        const float er = g0r[k] * g1r[k] + g0i[k] * g1i[k];   // Re(conj(g0) g1)
        const float ei = g0r[k] * g1i[k] - g0i[k] * g1r[k];   // Im(conj(g0) g1)
        const float4 MZ = __ldg(&g_MZh[k]);
        const float4 MX = __ldg(&g_MXh[k]);

        // Z suffix step
        z = sandwich_m(z, n0, n1, er, ei, MZ);
        Zs[k] = z;

        // X-pair object: XX_k = MX_k-sandwich of XA_{k+1}
        if (k <= 8) XX[k] = sandwich_m(xa_prev, n0, n1, er, ei, MX);

        // XA_k = MX_k-step from diagonal suffix S_{k+1} (current sA, sB)
        xa_prev = diagstep_m(sA, sB, n0, n1, er, ei, MX);

        // identity diag update: S_k
        const float nA = n0 * sA + n1 * sB;
        const float nB = n1 * sA + n0 * sB;
        sA = nA; sB = nB;
    }
    const H XA0 = xa_prev;   // lone X on bit 0 (wire 9)

    // ---- prefix sweep with fused feature dots ----
    float la = 1.f, lbr = 1.f, lbi = 0.f, lc = 1.f;   // L_0: all-ones (Hermitian repr)
    float acc = 0.f;

    // k = 0 features use L_0 directly
    acc += __ldg(&head_w[19]) * (XA0.a + XA0.c + 2.f * XA0.br);

    #pragma unroll
    for (int k = 0; k < NW; ++k) {
        // Z feature, wire 9-k
        acc += __ldg(&head_w[9 - k]) * hdot(la, lbr, lbi, lc, Zs[k]);
        // X-pair feature, wire 8-k
        if (k <= 8) acc += __ldg(&head_w[18 - k]) * hdot(la, lbr, lbi, lc, XX[k]);

        // advance L (identity site k): uses only diag of L
        if (k < 9) {
            const float n0 = g0r[k] * g0r[k] + g0i[k] * g0i[k];
            const float n1 = g1r[k] * g1r[k] + g1i[k] * g1i[k];
            const float er = g0r[k] * g1r[k] + g0i[k] * g1i[k];
            const float ei = g0r[k] * g1i[k] - g0i[k] * g1r[k];
            const float nla = n0 * la + n1 * lc;
            const float nlc = n1 * la + n0 * lc;
            lbr = (la + lc) * er;
            lbi = (la - lc) * ei;
            la = nla; lc = nlc;
        }
    }

    out[b] = acc + __ldg(head_b);
}

extern "C" void kernel_launch(void* const* d_in, const int* in_sizes, int n_in,
                              void* d_out, int out_size) {
    const float* x      = (const float*)d_in[0];  // (B,10)
    const float* params = (const float*)d_in[1];  // (60,)
    const float* hw     = (const float*)d_in[2];  // (20,)
    const float* hb     = (const float*)d_in[3];  // (1,)
    float* out = (float*)d_out;
    const int B = in_sizes[0] / NW;               // 4096

    prep_kernel<<<1, 32>>>(params);
    qreg_kernel<<<(B + 31) / 32, 32>>>(x, hw, hb, out, B);
}

// round 9
// speedup vs baseline: 3.5300x; 1.1982x over previous
#include <cuda_runtime.h>

#define FULL 0xffffffffu
#define NW 10

// Hermitian 2x2: (a, br, bi, c) = [[a, b],[conj(b), c]], a/c real.
struct H { float a, br, bi, c; };

__device__ __forceinline__ H sandwich_m(const H r, float n0, float n1, float er, float ei,
                                        float m00, float m01r, float m01i, float m11) {
    const float cm = er * r.br - ei * r.bi;   // Re(e * b)
    const float cp = er * r.br + ei * r.bi;   // Re(e * conj(b))
    const float t00 = n0 * r.a + n1 * r.c + 2.f * cm;
    const float t11 = n1 * r.a + n0 * r.c + 2.f * cp;
    const float t01r = (r.a + r.c) * er + (n0 + n1) * r.br;
    const float t01i = (r.a - r.c) * ei + (n0 - n1) * r.bi;
    H o;
    o.a  = m00 * t00;
    o.c  = m11 * t11;
    o.br = m01r * t01r - m01i * t01i;
    o.bi = m01r * t01i + m01i * t01r;
    return o;
}

__device__ __forceinline__ H diagstep_m(float sA, float sB, float n0, float n1,
                                        float er, float ei,
                                        float m00, float m01r, float m01i, float m11) {
    const float t00 = n0 * sA + n1 * sB;
    const float t11 = n1 * sA + n0 * sB;
    const float t01r = (sA + sB) * er;
    const float t01i = (sA - sB) * ei;
    H o;
    o.a  = m00 * t00;
    o.c  = m11 * t11;
    o.br = m01r * t01r - m01i * t01i;
    o.bi = m01r * t01i + m01i * t01r;
    return o;
}

__device__ __forceinline__ float hdot(float la, float lbr, float lbi, float lc, const H r) {
    return la * r.a + lc * r.c + 2.f * (lbr * r.br - lbi * r.bi);
}

__global__ __launch_bounds__(64) void qreg_kernel(
    const float* __restrict__ x,        // (B, 10)
    const float* __restrict__ params,   // (60,)
    const float* __restrict__ head_w,   // (20,)
    const float* __restrict__ head_b,   // (1,)
    float* __restrict__ out,            // (B,)
    int B)
{
    const int lane = threadIdx.x & 31;
    const int gw   = (blockIdx.x * blockDim.x + threadIdx.x) >> 5;
    const int role = lane & 1;              // 0 = Z features, 1 = X features
    const int b    = gw * 16 + (lane >> 1); // sample index
    const int bc   = (b < B) ? b : (B - 1); // clamped for loads (no early return: shuffles)

    // ================= per-warp prep (redundant across warps) =================
    // lanes 0..9   : r1[8] = layer-1 Rot (wire = lane), Mh = MZh (bit = lane)
    // lanes 16..25 : Mh = MXh (bit = lane - 16)
    float r1[8] = {0, 0, 0, 0, 0, 0, 0, 0};
    float4 Mh = make_float4(0.f, 0.f, 0.f, 0.f);
    {
        const bool lz = (lane < NW);
        const bool lx = (lane >= 16 && lane < 16 + NW);
        if (lz) {
            const int w = lane;
            const float phi = __ldg(&params[w * 3 + 0]);
            const float th  = __ldg(&params[w * 3 + 1]);
            const float om  = __ldg(&params[w * 3 + 2]);
            float ct, st, cp, sp, cm, sm;
            sincosf(0.5f * th, &st, &ct);
            sincosf(0.5f * (phi + om), &sp, &cp);
            sincosf(0.5f * (phi - om), &sm, &cm);
            r1[0] =  ct * cp;  r1[1] = -ct * sp;
            r1[2] = -st * cm;  r1[3] = -st * sm;
            r1[4] =  st * cm;  r1[5] = -st * sm;
            r1[6] =  ct * cp;  r1[7] =  ct * sp;
        }
        if (lz || lx) {
            // layer-2 gate on bit k is the Rot of wire 9-k
            const int bit = lz ? lane : (lane - 16);
            const int w2  = 9 - bit;
            const float phi = __ldg(&params[(NW + w2) * 3 + 0]);
            const float th  = __ldg(&params[(NW + w2) * 3 + 1]);
            const float om  = __ldg(&params[(NW + w2) * 3 + 2]);
            float ct, st, cp, sp, cm, sm;
            sincosf(0.5f * th, &st, &ct);
            sincosf(0.5f * (phi + om), &sp, &cp);
            sincosf(0.5f * (phi - om), &sm, &cm);
            const float U00r =  ct * cp, U00i = -ct * sp;
            const float U01r = -st * cm, U01i = -st * sm;
            const float U10r =  st * cm, U10i = -st * sm;
            const float U11r =  ct * cp, U11i =  ct * sp;
            if (lz) {
                // MZ = U^H Z U
                Mh.x = (U00r * U00r + U00i * U00i) - (U10r * U10r + U10i * U10i);
                Mh.w = (U01r * U01r + U01i * U01i) - (U11r * U11r + U11i * U11i);
                Mh.y = (U00r * U01r + U00i * U01i) - (U10r * U11r + U10i * U11i);
                Mh.z = (U00r * U01i - U00i * U01r) - (U10r * U11i - U10i * U11r);
            } else {
                // MX = U^H X U
                Mh.x = 2.f * (U00r * U10r + U00i * U10i);
                Mh.w = 2.f * (U01r * U11r + U01i * U11i);
                Mh.y = (U00r * U11r + U00i * U11i) + (U10r * U01r + U10i * U01i);
                Mh.z = (U00r * U11i - U00i * U11r) + (U10r * U01i - U10i * U01r);
            }
        }
    }

    // ================= per-sample site constants (both roles) =================
    float n0[NW], n1[NW], er[NW], ei[NW];
    #pragma unroll
    for (int w = 0; w < NW; ++w) {
        float cx, sx;
        __sincosf(0.5f * __ldg(&x[bc * NW + w]), &sx, &cx);
        // layer-1 Rot of wire w via broadcast from lane w
        const float u00r = __shfl_sync(FULL, r1[0], w);
        const float u00i = __shfl_sync(FULL, r1[1], w);
        const float u01r = __shfl_sync(FULL, r1[2], w);
        const float u01i = __shfl_sync(FULL, r1[3], w);
        const float u10r = __shfl_sync(FULL, r1[4], w);
        const float u10i = __shfl_sync(FULL, r1[5], w);
        const float u11r = __shfl_sync(FULL, r1[6], w);
        const float u11i = __shfl_sync(FULL, r1[7], w);
        const float g0r = u00r * cx + u01r * sx;
        const float g0i = u00i * cx + u01i * sx;
        const float g1r = u10r * cx + u11r * sx;
        const float g1i = u10i * cx + u11i * sx;
        const int k = 9 - w;
        n0[k] = g0r * g0r + g0i * g0i;
        n1[k] = g1r * g1r + g1i * g1i;
        er[k] = g0r * g1r + g0i * g1i;   // Re(conj(g0) g1)
        ei[k] = g0r * g1i - g0i * g1r;   // Im(conj(g0) g1)
    }

    // ================= suffix sweep, role-split =================
    // even (role 0): carry = Z chain; store[k] = Zs[k]
    // odd  (role 1): carry = XA chain; store[k] = XX[k] (k<=8); store[9] = XA0 after loop
    H store[NW];
    H carry; carry.a = 1.f; carry.br = 0.f; carry.bi = 0.f; carry.c = 0.f;
    float sA = 1.f, sB = 0.f;

    #pragma unroll
    for (int k = 9; k >= 0; --k) {
        // role-selected M: even reads lane k (MZ), odd reads lane 16+k (MX)
        const int src = k + (role << 4);
        const float m00  = __shfl_sync(FULL, Mh.x, src);
        const float m01r = __shfl_sync(FULL, Mh.y, src);
        const float m01i = __shfl_sync(FULL, Mh.z, src);
        const float m11  = __shfl_sync(FULL, Mh.w, src);

        const H sw = sandwich_m(carry, n0[k], n1[k], er[k], ei[k], m00, m01r, m01i, m11);
        const H dg = diagstep_m(sA, sB, n0[k], n1[k], er[k], ei[k], m00, m01r, m01i, m11);

        if (role == 0) {
            carry = sw;
            store[k] = sw;                       // Zs[k]
        } else {
            if (k <= 8) store[k] = sw;           // XX[k] (k=9 value discarded)
            carry = dg;                          // XA_k
        }
        // identity diag suffix S (used by odd; harmless for even)
        const float nA = n0[k] * sA + n1[k] * sB;
        const float nB = n1[k] * sA + n0[k] * sB;
        sA = nA; sB = nB;
    }
    if (role) store[9] = carry;                  // XA0 (lone X on bit 0, wire 9)

    // ================= prefix sweep with fused feature dots =================
    float la = 1.f, lbr = 1.f, lbi = 0.f, lc = 1.f;   // L_0 = all-ones (Hermitian repr)
    float acc = 0.f;
    if (role)
        acc = __ldg(&head_w[19]) * (store[9].a + store[9].c + 2.f * store[9].br);

    #pragma unroll
    for (int k = 0; k < NW; ++k) {
        const int wi = role ? (18 - k) : (9 - k);
        float wv = __ldg(&head_w[(wi < 0) ? 0 : wi]);
        if (role && k == 9) wv = 0.f;            // no X-pair at k=9
        acc += wv * hdot(la, lbr, lbi, lc, store[k]);

        if (k < 9) {
            const float nla = n0[k] * la + n1[k] * lc;
            const float nlc = n1[k] * la + n0[k] * lc;
            lbr = (la + lc) * er[k];
            lbi = (la - lc) * ei[k];
            la = nla; lc = nlc;
        }
    }

    // pair reduction: even + odd
    acc += __shfl_xor_sync(FULL, acc, 1);
    if (role == 0 && b < B) out[b] = acc + __ldg(head_b);
}

extern "C" void kernel_launch(void* const* d_in, const int* in_sizes, int n_in,
                              void* d_out, int out_size) {
    const float* x      = (const float*)d_in[0];  // (B,10)
    const float* params = (const float*)d_in[1];  // (60,)
    const float* hw     = (const float*)d_in[2];  // (20,)
    const float* hb     = (const float*)d_in[3];  // (1,)
    float* out = (float*)d_out;
    const int B = in_sizes[0] / NW;               // 4096

    const int threads = 2 * B;                    // 2 lanes per sample
    const int blk = 64;
    qreg_kernel<<<(threads + blk - 1) / blk, blk>>>(x, params, hw, hb, out, B);
}

// round 10
// speedup vs baseline: 3.5794x; 1.0140x over previous
#include <cuda_runtime.h>

#define FULL 0xffffffffu
#define NW 10

// Hermitian 2x2: (a, br, bi, c) = [[a, b],[conj(b), c]], a/c real.
struct H { float a, br, bi, c; };

__device__ __forceinline__ H sandwich_m(const H r, float n0, float n1, float er, float ei,
                                        float m00, float m01r, float m01i, float m11) {
    const float cm = er * r.br - ei * r.bi;   // Re(e * b)
    const float cp = er * r.br + ei * r.bi;   // Re(e * conj(b))
    const float t00 = n0 * r.a + n1 * r.c + 2.f * cm;
    const float t11 = n1 * r.a + n0 * r.c + 2.f * cp;
    const float t01r = (r.a + r.c) * er + (n0 + n1) * r.br;
    const float t01i = (r.a - r.c) * ei + (n0 - n1) * r.bi;
    H o;
    o.a  = m00 * t00;
    o.c  = m11 * t11;
    o.br = m01r * t01r - m01i * t01i;
    o.bi = m01r * t01i + m01i * t01r;
    return o;
}

__device__ __forceinline__ H diagstep_m(float sA, float sB, float n0, float n1,
                                        float er, float ei,
                                        float m00, float m01r, float m01i, float m11) {
    const float t00 = n0 * sA + n1 * sB;
    const float t11 = n1 * sA + n0 * sB;
    const float t01r = (sA + sB) * er;
    const float t01i = (sA - sB) * ei;
    H o;
    o.a  = m00 * t00;
    o.c  = m11 * t11;
    o.br = m01r * t01r - m01i * t01i;
    o.bi = m01r * t01i + m01i * t01r;
    return o;
}

__device__ __forceinline__ float hdot(float la, float lbr, float lbi, float lc, const H r) {
    return la * r.a + lc * r.c + 2.f * (lbr * r.br - lbi * r.bi);
}

__global__ __launch_bounds__(64) void qreg_kernel(
    const float* __restrict__ x,        // (B, 10)
    const float* __restrict__ params,   // (60,)
    const float* __restrict__ head_w,   // (20,)
    const float* __restrict__ head_b,   // (1,)
    float* __restrict__ out,            // (B,)
    int B)
{
    const int lane = threadIdx.x & 31;
    const int gw   = (blockIdx.x * blockDim.x + threadIdx.x) >> 5;
    const int role = lane & 1;              // 0 = Z features, 1 = X features
    const int b    = gw * 16 + (lane >> 1); // sample index
    const int bc   = (b < B) ? b : (B - 1); // clamped (no early return: warp shuffles)

    // ================= per-warp prep (redundant across warps) =================
    // lanes 0..9   : r1[8] = layer-1 Rot (wire = lane), Mh = MZh (bit = lane)
    // lanes 16..25 : Mh = MXh (bit = lane - 16)
    float r1[8] = {0, 0, 0, 0, 0, 0, 0, 0};
    float4 Mh = make_float4(0.f, 0.f, 0.f, 0.f);
    {
        const bool lz = (lane < NW);
        const bool lx = (lane >= 16 && lane < 16 + NW);
        if (lz) {
            const int w = lane;
            const float phi = __ldg(&params[w * 3 + 0]);
            const float th  = __ldg(&params[w * 3 + 1]);
            const float om  = __ldg(&params[w * 3 + 2]);
            float ct, st, cp, sp, cm, sm;
            sincosf(0.5f * th, &st, &ct);
            sincosf(0.5f * (phi + om), &sp, &cp);
            sincosf(0.5f * (phi - om), &sm, &cm);
            r1[0] =  ct * cp;  r1[1] = -ct * sp;
            r1[2] = -st * cm;  r1[3] = -st * sm;
            r1[4] =  st * cm;  r1[5] = -st * sm;
            r1[6] =  ct * cp;  r1[7] =  ct * sp;
        }
        if (lz || lx) {
            // layer-2 gate on bit k is the Rot of wire 9-k
            const int bit = lz ? lane : (lane - 16);
            const int w2  = 9 - bit;
            const float phi = __ldg(&params[(NW + w2) * 3 + 0]);
            const float th  = __ldg(&params[(NW + w2) * 3 + 1]);
            const float om  = __ldg(&params[(NW + w2) * 3 + 2]);
            float ct, st, cp, sp, cm, sm;
            sincosf(0.5f * th, &st, &ct);
            sincosf(0.5f * (phi + om), &sp, &cp);
            sincosf(0.5f * (phi - om), &sm, &cm);
            const float U00r =  ct * cp, U00i = -ct * sp;
            const float U01r = -st * cm, U01i = -st * sm;
            const float U10r =  st * cm, U10i = -st * sm;
            const float U11r =  ct * cp, U11i =  ct * sp;
            if (lz) {
                // MZ = U^H Z U
                Mh.x = (U00r * U00r + U00i * U00i) - (U10r * U10r + U10i * U10i);
                Mh.w = (U01r * U01r + U01i * U01i) - (U11r * U11r + U11i * U11i);
                Mh.y = (U00r * U01r + U00i * U01i) - (U10r * U11r + U10i * U11i);
                Mh.z = (U00r * U01i - U00i * U01r) - (U10r * U11i - U10i * U11r);
            } else {
                // MX = U^H X U
                Mh.x = 2.f * (U00r * U10r + U00i * U10i);
                Mh.w = 2.f * (U01r * U11r + U01i * U11i);
                Mh.y = (U00r * U11r + U00i * U11i) + (U10r * U01r + U10i * U01i);
                Mh.z = (U00r * U11i - U00i * U11r) + (U10r * U01i - U10i * U01r);
            }
        }
    }

    // ---- hoisted role-selected M table (burst of independent shuffles) ----
    float m00[NW], m01r[NW], m01i[NW], m11[NW];
    #pragma unroll
    for (int k = 0; k < NW; ++k) {
        const int src = k + (role << 4);
        m00[k]  = __shfl_sync(FULL, Mh.x, src);
        m01r[k] = __shfl_sync(FULL, Mh.y, src);
        m01i[k] = __shfl_sync(FULL, Mh.z, src);
        m11[k]  = __shfl_sync(FULL, Mh.w, src);
    }

    // ---- vectorized x load + sincos burst (independent MUFU pipeline) ----
    float cx[NW], sx[NW];
    {
        const float2* xp = (const float2*)(x + bc * NW);   // 8B-aligned (40B rows)
        float xa[NW];
        #pragma unroll
        for (int i = 0; i < 5; ++i) {
            const float2 v = __ldg(&xp[i]);
            xa[2 * i] = v.x; xa[2 * i + 1] = v.y;
        }
        #pragma unroll
        for (int w = 0; w < NW; ++w)
            __sincosf(0.5f * xa[w], &sx[w], &cx[w]);
    }

    // ---- per-sample site constants (bit k <-> wire 9-k) ----
    float n0[NW], n1[NW], er[NW], ei[NW];
    #pragma unroll
    for (int w = 0; w < NW; ++w) {
        const float u00r = __shfl_sync(FULL, r1[0], w);
        const float u00i = __shfl_sync(FULL, r1[1], w);
        const float u01r = __shfl_sync(FULL, r1[2], w);
        const float u01i = __shfl_sync(FULL, r1[3], w);
        const float u10r = __shfl_sync(FULL, r1[4], w);
        const float u10i = __shfl_sync(FULL, r1[5], w);
        const float u11r = __shfl_sync(FULL, r1[6], w);
        const float u11i = __shfl_sync(FULL, r1[7], w);
        const float g0r = u00r * cx[w] + u01r * sx[w];
        const float g0i = u00i * cx[w] + u01i * sx[w];
        const float g1r = u10r * cx[w] + u11r * sx[w];
        const float g1i = u10i * cx[w] + u11i * sx[w];
        const int k = 9 - w;
        n0[k] = g0r * g0r + g0i * g0i;
        n1[k] = g1r * g1r + g1i * g1i;
        er[k] = g0r * g1r + g0i * g1i;   // Re(conj(g0) g1)
        ei[k] = g0r * g1i - g0i * g1r;   // Im(conj(g0) g1)
    }

    // ================= suffix sweep, role-split (shared sandwich) =================
    // even (role 0): carry = Z chain; store[k] = Zs[k]
    // odd  (role 1): carry = XA chain; store[k] = XX[k] (k<=8); store[9] = XA0
    H store[NW];
    H carry; carry.a = 1.f; carry.br = 0.f; carry.bi = 0.f; carry.c = 0.f;
    float sA = 1.f, sB = 0.f;

    #pragma unroll
    for (int k = 9; k >= 0; --k) {
        const H sw = sandwich_m(carry, n0[k], n1[k], er[k], ei[k],
                                m00[k], m01r[k], m01i[k], m11[k]);
        const H dg = diagstep_m(sA, sB, n0[k], n1[k], er[k], ei[k],
                                m00[k], m01r[k], m01i[k], m11[k]);
        if (role == 0) {
            carry = sw;
            store[k] = sw;                       // Zs[k]
        } else {
            if (k <= 8) store[k] = sw;           // XX[k] (k=9 value discarded)
            carry = dg;                          // XA_k
        }
        const float nA = n0[k] * sA + n1[k] * sB;
        const float nB = n1[k] * sA + n0[k] * sB;
        sA = nA; sB = nB;
    }
    if (role) store[9] = carry;                  // XA0 (lone X on bit 0, wire 9)

    // ================= prefix sweep with fused feature dots =================
    float la = 1.f, lbr = 1.f, lbi = 0.f, lc = 1.f;   // L_0 = all-ones
    float acc = 0.f;
    if (role)
        acc = __ldg(&head_w[19]) * (store[9].a + store[9].c + 2.f * store[9].br);

    #pragma unroll
    for (int k = 0; k < NW; ++k) {
        const int wi = role ? (18 - k) : (9 - k);
        float wv = __ldg(&head_w[(wi < 0) ? 0 : wi]);
        if (role && k == 9) wv = 0.f;            // no X-pair at k=9
        acc += wv * hdot(la, lbr, lbi, lc, store[k]);

        if (k < 9) {
            const float nla = n0[k] * la + n1[k] * lc;
            const float nlc = n1[k] * la + n0[k] * lc;
            lbr = (la + lc) * er[k];
            lbi = (la - lc) * ei[k];
            la = nla; lc = nlc;
        }
    }

    // pair reduction: even + odd
    acc += __shfl_xor_sync(FULL, acc, 1);
    if (role == 0 && b < B) out[b] = acc + __ldg(head_b);
}

extern "C" void kernel_launch(void* const* d_in, const int* in_sizes, int n_in,
                              void* d_out, int out_size) {
    const float* x      = (const float*)d_in[0];  // (B,10)
    const float* params = (const float*)d_in[1];  // (60,)
    const float* hw     = (const float*)d_in[2];  // (20,)
    const float* hb     = (const float*)d_in[3];  // (1,)
    float* out = (float*)d_out;
    const int B = in_sizes[0] / NW;               // 4096

    const int threads = 2 * B;                    // 2 lanes per sample
    const int blk = 64;
    qreg_kernel<<<(threads + blk - 1) / blk, blk>>>(x, params, hw, hb, out, B);
}